// round 7
// baseline (speedup 1.0000x reference)
#include <cuda_runtime.h>
#include <cuda_fp16.h>
#include <math.h>
#include <stdint.h>

// ---------------------------------------------------------------------------
// MoE block via mma.sync fp16 (fp32 accum), ldmatrix, 64x64 warp tiles,
// 3-stage cp.async pipeline. tcgen05 unavailable (toolchain targets sm_103).
// ---------------------------------------------------------------------------

#define NEXP 8
#define DM 768
#define MLPD 3072
#define CAP_DET 256
#define CAP_CLS 32
#define RPE 2304
#define MTOT (NEXP * RPE)
#define NTOK_DET 8192
#define NTOK_CLS 1024
#define NTOK (NTOK_DET + NTOK_CLS)

#define CHUNK 64                        // K halves per pipeline stage
#define SSTR 72                         // padded smem row stride (halves)
#define TILE_HALVES (128 * SSTR)
#define STAGE_HALVES (2 * TILE_HALVES)
#define NBUF 3
#define SMEM_DYN (NBUF * STAGE_HALVES * 2)   // 110592 bytes

// --------------------------- scratch ---------------------------------------
__device__ __half g_xg[(size_t)MTOT * DM];
__device__ __half g_h [(size_t)MTOT * MLPD];
__device__ __half g_ye[(size_t)MTOT * DM];
__device__ __half g_w1t[(size_t)NEXP * MLPD * DM];   // [E, N=3072, K=768]
__device__ __half g_w2t[(size_t)NEXP * DM * MLPD];   // [E, N=768,  K=3072]
__device__ float  g_wrt[2][NEXP * DM];
__device__ int    g_row_src[MTOT];
__device__ signed char g_tok_e[NTOK][2];
__device__ float  g_tok_p[NTOK][2];
__device__ int    g_tok_rows[NTOK][2];
__device__ float  g_tok_g[NTOK][2];

// --------------------------- helpers ---------------------------------------
__device__ __forceinline__ uint32_t smem_u32(const void* p) {
    uint32_t a;
    asm("{ .reg .u64 t; cvta.to.shared.u64 t, %1; cvt.u32.u64 %0, t; }"
        : "=r"(a) : "l"(p));
    return a;
}
__device__ __forceinline__ void cp_async16(uint32_t sdst, const void* gsrc) {
    asm volatile("cp.async.cg.shared.global [%0], [%1], 16;"
                 :: "r"(sdst), "l"(gsrc) : "memory");
}
__device__ __forceinline__ void cp_commit() {
    asm volatile("cp.async.commit_group;" ::: "memory");
}
template<int N>
__device__ __forceinline__ void cp_wait() {
    asm volatile("cp.async.wait_group %0;" :: "n"(N) : "memory");
}
__device__ __forceinline__ void ldsm_x4(uint32_t* r, uint32_t addr) {
    asm volatile("ldmatrix.sync.aligned.m8n8.x4.shared.b16 {%0,%1,%2,%3}, [%4];"
                 : "=r"(r[0]), "=r"(r[1]), "=r"(r[2]), "=r"(r[3]) : "r"(addr));
}
__device__ __forceinline__ void mma_f16(float* d, const uint32_t* a,
                                        const uint32_t* b) {
    asm volatile(
        "mma.sync.aligned.m16n8k16.row.col.f32.f16.f16.f32 "
        "{%0,%1,%2,%3}, {%4,%5,%6,%7}, {%8,%9}, {%0,%1,%2,%3};"
        : "+f"(d[0]), "+f"(d[1]), "+f"(d[2]), "+f"(d[3])
        : "r"(a[0]), "r"(a[1]), "r"(a[2]), "r"(a[3]),
          "r"(b[0]), "r"(b[1]));
}
__device__ __forceinline__ float gelu_tanh(float x) {
    float x3 = x * x * x;
    return 0.5f * x * (1.0f + tanhf(0.7978845608028654f * (x + 0.044715f * x3)));
}

// --------------------------- init ------------------------------------------
__global__ void init_kernel() {
    int i = blockIdx.x * blockDim.x + threadIdx.x;
    if (i < MTOT) g_row_src[i] = -1;
    if (i < NTOK * 2) {
        ((int*)g_tok_rows)[i] = -1;
        ((float*)g_tok_g)[i] = 0.0f;
    }
}

// ----------------- router weight transpose [D,E] -> [E,D] -------------------
__global__ void wr_transpose_kernel(const float* __restrict__ wr0,
                                    const float* __restrict__ wr1) {
    int i = blockIdx.x * blockDim.x + threadIdx.x;
    if (i >= DM * NEXP) return;
    int d = i / NEXP, e = i % NEXP;
    g_wrt[0][e * DM + d] = wr0[i];
    g_wrt[1][e * DM + d] = wr1[i];
}

// --------------------------- router ----------------------------------------
__global__ void router_kernel(const float* __restrict__ x,
                              int which, int n_tokens, int tok_base) {
    int gwarp = (blockIdx.x * blockDim.x + threadIdx.x) >> 5;
    int lane  = threadIdx.x & 31;
    if (gwarp >= n_tokens) return;
    const float4* xr = (const float4*)(x + (size_t)gwarp * DM);
    const float* wt = g_wrt[which];

    float acc[NEXP];
#pragma unroll
    for (int e = 0; e < NEXP; e++) acc[e] = 0.f;
#pragma unroll
    for (int it = 0; it < 6; it++) {
        int d4 = it * 32 + lane;
        float4 xv = xr[d4];
#pragma unroll
        for (int e = 0; e < NEXP; e++) {
            float4 wv = ((const float4*)(wt + e * DM))[d4];
            acc[e] += xv.x * wv.x + xv.y * wv.y + xv.z * wv.z + xv.w * wv.w;
        }
    }
#pragma unroll
    for (int e = 0; e < NEXP; e++) {
#pragma unroll
        for (int off = 16; off > 0; off >>= 1)
            acc[e] += __shfl_xor_sync(0xffffffffu, acc[e], off);
    }
    if (lane == 0) {
        float mx = acc[0];
#pragma unroll
        for (int e = 1; e < NEXP; e++) mx = fmaxf(mx, acc[e]);
        float p[NEXP]; float s = 0.f;
#pragma unroll
        for (int e = 0; e < NEXP; e++) { p[e] = expf(acc[e] - mx); s += p[e]; }
        float inv = 1.0f / s;
        int e0 = 0;
#pragma unroll
        for (int e = 1; e < NEXP; e++) if (p[e] > p[e0]) e0 = e;
        int e1 = (e0 == 0) ? 1 : 0;
#pragma unroll
        for (int e = 0; e < NEXP; e++) if (e != e0 && p[e] > p[e1]) e1 = e;
        int t = tok_base + gwarp;
        g_tok_e[t][0] = (signed char)e0;
        g_tok_e[t][1] = (signed char)e1;
        g_tok_p[t][0] = p[e0] * inv;
        g_tok_p[t][1] = p[e1] * inv;
    }
}

// ------------------ positions (rank-major cumsum + capacity) ----------------
__global__ void positions_kernel(int S, int C, int tok_base, int row_off) {
    __shared__ signed char se0[1024], se1[1024];
    __shared__ float sg0[1024], sg1[1024];
    int g = blockIdx.x;
    int tid = threadIdx.x;
    for (int t = tid; t < S; t += blockDim.x) {
        int gt = tok_base + g * S + t;
        se0[t] = g_tok_e[gt][0];
        se1[t] = g_tok_e[gt][1];
        sg0[t] = g_tok_p[gt][0];
        sg1[t] = g_tok_p[gt][1];
    }
    __syncthreads();
    int e = tid >> 5;
    int lane = tid & 31;
    int base = 0;
    int total = 2 * S;
    for (int j0 = 0; j0 < total; j0 += 32) {
        int j = j0 + lane;
        int exp_j = -1;
        if (j < total) exp_j = (j < S) ? (int)se0[j] : (int)se1[j - S];
        bool m = (exp_j == e);
        unsigned mask = __ballot_sync(0xffffffffu, m);
        if (m) {
            int pos = base + __popc(mask & ((1u << lane) - 1u));
            if (pos < C) {
                int t = (j < S) ? j : (j - S);
                int r = (j < S) ? 0 : 1;
                int gt = tok_base + g * S + t;
                float gate = (r == 0) ? sg0[t] : sg1[t];
                int row = e * RPE + row_off + g * C + pos;
                g_row_src[row] = gt;
                g_tok_rows[gt][r] = row;
                g_tok_g[gt][r] = gate;
            }
        }
        base += __popc(mask);
    }
}

// ------------------- weight transpose (fp32 -> half) ------------------------
__global__ void transpose_kernel(const float* __restrict__ src,
                                 __half* __restrict__ dst, int K, int N) {
    __shared__ float tile[32][33];
    int e = blockIdx.z;
    int n0 = blockIdx.x * 32, k0 = blockIdx.y * 32;
    int tx = threadIdx.x, ty = threadIdx.y;
    const float* S = src + (size_t)e * K * N;
    __half* D = dst + (size_t)e * N * K;
#pragma unroll
    for (int r = 0; r < 32; r += 8)
        tile[ty + r][tx] = S[(size_t)(k0 + ty + r) * N + n0 + tx];
    __syncthreads();
#pragma unroll
    for (int r = 0; r < 32; r += 8)
        D[(size_t)(n0 + ty + r) * K + k0 + tx] = __float2half_rn(tile[tx][ty + r]);
}

// --------------------------- gather (fp32 -> half) ---------------------------
__global__ void gather_kernel(const float* __restrict__ xdet,
                              const float* __restrict__ xcls) {
    int row = blockIdx.x;
    int i = threadIdx.x;
    int src = g_row_src[row];
    __half2 h0 = __half2half2(__float2half_rn(0.f));
    __half2 h1 = h0;
    if (src >= 0) {
        const float* xp = (src < NTOK_DET)
            ? (xdet + (size_t)src * DM)
            : (xcls + (size_t)(src - NTOK_DET) * DM);
        float4 v = ((const float4*)xp)[i];
        h0 = __floats2half2_rn(v.x, v.y);
        h1 = __floats2half2_rn(v.z, v.w);
    }
    __half2* dst = (__half2*)(g_xg + (size_t)row * DM) + i * 2;
    dst[0] = h0;
    dst[1] = h1;
}

// --------------------------- mma.sync fp16 GEMM ------------------------------
// 128x128 CTA tile, 128 threads (2x2 warps, 64x64 per warp),
// CHUNK=64 halves, 3-stage cp.async pipeline, ldmatrix fragment loads.
template<int K, int NTOT, bool GELU>
__device__ __forceinline__ void tc_gemm(const __half* __restrict__ A,
                                        const __half* __restrict__ WT,
                                        const float* __restrict__ bias,
                                        __half* __restrict__ C) {
    extern __shared__ __half smem[];
    int tid = threadIdx.x;
    int wid = tid >> 5, lane = tid & 31;
    int gid = lane >> 2, tig = lane & 3;
    int warp_m = wid & 1, warp_n = wid >> 1;
    int m_base = warp_m * 64, n_base = warp_n * 64;
    int bx = blockIdx.x, by = blockIdx.y;
    int e = (by * 128) / RPE;
    const __half* Ab = A + (size_t)by * 128 * K;
    const __half* Wb = WT + ((size_t)e * NTOT + (size_t)bx * 128) * K;

    uint32_t a_off = (uint32_t)((m_base + (lane & 15)) * SSTR + ((lane >> 4) << 3));
    uint32_t b_off = (uint32_t)((n_base + (((lane >> 4) & 1) << 3) + (lane & 7)) * SSTR
                                + (((lane >> 3) & 1) << 3));

    float acc[4][8][4];
#pragma unroll
    for (int mi = 0; mi < 4; mi++)
#pragma unroll
        for (int ni = 0; ni < 8; ni++)
#pragma unroll
            for (int q = 0; q < 4; q++) acc[mi][ni][q] = 0.f;

    const int NC = K / CHUNK;
    uint32_t sbase = smem_u32(smem);

    auto issue_stage = [&](int c) {
        int buf = c % NBUF;
        uint32_t as = sbase + (uint32_t)(buf * STAGE_HALVES) * 2u;
        uint32_t bs = as + (uint32_t)TILE_HALVES * 2u;
        int kc = c * CHUNK;
#pragma unroll
        for (int j = 0; j < 8; j++) {
            int idx = j * 128 + tid;          // 1024 x 16B per operand
            int row = idx >> 3, seg = idx & 7;
            cp_async16(as + (uint32_t)(row * SSTR + seg * 8) * 2u,
                       Ab + (size_t)row * K + kc + seg * 8);
        }
#pragma unroll
        for (int j = 0; j < 8; j++) {
            int idx = j * 128 + tid;
            int row = idx >> 3, seg = idx & 7;
            cp_async16(bs + (uint32_t)(row * SSTR + seg * 8) * 2u,
                       Wb + (size_t)row * K + kc + seg * 8);
        }
        cp_commit();
    };

    issue_stage(0);
    if (NC > 1) issue_stage(1);
    for (int c = 0; c < NC; c++) {
        if (c + 2 < NC) { issue_stage(c + 2); cp_wait<2>(); }
        else if (c + 1 < NC) { cp_wait<1>(); }
        else { cp_wait<0>(); }
        __syncthreads();

        uint32_t as = sbase + (uint32_t)((c % NBUF) * STAGE_HALVES) * 2u;
        uint32_t bs = as + (uint32_t)TILE_HALVES * 2u;
        uint32_t a_base = as + a_off * 2u;
        uint32_t b_base = bs + b_off * 2u;
#pragma unroll
        for (int kk = 0; kk < CHUNK; kk += 16) {
            uint32_t afr[4][4];
#pragma unroll
            for (int mi = 0; mi < 4; mi++)
                ldsm_x4(afr[mi], a_base + (uint32_t)(mi * 16 * SSTR + kk) * 2u);
            uint32_t bfr[4][4];
#pragma unroll
            for (int p = 0; p < 4; p++)
                ldsm_x4(bfr[p], b_base + (uint32_t)(p * 16 * SSTR + kk) * 2u);
#pragma unroll
            for (int mi = 0; mi < 4; mi++)
#pragma unroll
                for (int ni = 0; ni < 8; ni++)
                    mma_f16(acc[mi][ni], afr[mi], &bfr[ni >> 1][(ni & 1) * 2]);
        }
        __syncthreads();
    }

#pragma unroll
    for (int ni = 0; ni < 8; ni++) {
        int cb = bx * 128 + n_base + ni * 8 + 2 * tig;
        float b0 = bias[e * NTOT + cb];
        float b1 = bias[e * NTOT + cb + 1];
#pragma unroll
        for (int mi = 0; mi < 4; mi++) {
            int r0 = by * 128 + m_base + mi * 16 + gid;
            float v0 = acc[mi][ni][0] + b0;
            float v1 = acc[mi][ni][1] + b1;
            float v2 = acc[mi][ni][2] + b0;
            float v3 = acc[mi][ni][3] + b1;
            if (GELU) {
                v0 = gelu_tanh(v0); v1 = gelu_tanh(v1);
                v2 = gelu_tanh(v2); v3 = gelu_tanh(v3);
            }
            *(__half2*)(C + (size_t)r0 * NTOT + cb)       = __floats2half2_rn(v0, v1);
            *(__half2*)(C + (size_t)(r0 + 8) * NTOT + cb) = __floats2half2_rn(v2, v3);
        }
    }
}

__global__ __launch_bounds__(128, 2)
void gemm1_tc(const float* __restrict__ b1) {
    tc_gemm<DM, MLPD, true>(g_xg, g_w1t, b1, g_h);
}
__global__ __launch_bounds__(128, 2)
void gemm2_tc(const float* __restrict__ b2) {
    tc_gemm<MLPD, DM, false>(g_h, g_w2t, b2, g_ye);
}

// --------------------------- scatter ----------------------------------------
__global__ void scatter_kernel(float* __restrict__ out) {
    int t = blockIdx.x;
    int i = threadIdx.x;                 // 192 threads, 4 elems each
    int r0 = g_tok_rows[t][0];
    int r1 = g_tok_rows[t][1];
    float ga = g_tok_g[t][0];
    float gb = g_tok_g[t][1];
    float4 acc = make_float4(0.f, 0.f, 0.f, 0.f);
    if (r0 >= 0) {
        const __half2* p = (const __half2*)(g_ye + (size_t)r0 * DM) + i * 2;
        float2 u = __half22float2(p[0]);
        float2 v = __half22float2(p[1]);
        acc.x = ga * u.x; acc.y = ga * u.y; acc.z = ga * v.x; acc.w = ga * v.y;
    }
    if (r1 >= 0) {
        const __half2* p = (const __half2*)(g_ye + (size_t)r1 * DM) + i * 2;
        float2 u = __half22float2(p[0]);
        float2 v = __half22float2(p[1]);
        acc.x += gb * u.x; acc.y += gb * u.y; acc.z += gb * v.x; acc.w += gb * v.y;
    }
    ((float4*)(out + (size_t)t * DM))[i] = acc;
}

// --------------------------- launch -----------------------------------------
extern "C" void kernel_launch(void* const* d_in, const int* in_sizes, int n_in,
                              void* d_out, int out_size) {
    (void)in_sizes; (void)n_in; (void)out_size;
    const float* xdet = (const float*)d_in[0];
    const float* xcls = (const float*)d_in[1];
    const float* wrd  = (const float*)d_in[2];
    const float* wrc  = (const float*)d_in[3];
    const float* w1   = (const float*)d_in[4];
    const float* b1   = (const float*)d_in[5];
    const float* w2   = (const float*)d_in[6];
    const float* b2   = (const float*)d_in[7];
    float* out = (float*)d_out;

    cudaFuncSetAttribute(gemm1_tc, cudaFuncAttributeMaxDynamicSharedMemorySize, SMEM_DYN);
    cudaFuncSetAttribute(gemm2_tc, cudaFuncAttributeMaxDynamicSharedMemorySize, SMEM_DYN);

    init_kernel<<<(MTOT + 255) / 256, 256>>>();
    wr_transpose_kernel<<<(DM * NEXP + 255) / 256, 256>>>(wrd, wrc);
    {
        __half* w1t; cudaGetSymbolAddress((void**)&w1t, g_w1t);
        __half* w2t; cudaGetSymbolAddress((void**)&w2t, g_w2t);
        transpose_kernel<<<dim3(MLPD / 32, DM / 32, NEXP), dim3(32, 8)>>>(w1, w1t, DM, MLPD);
        transpose_kernel<<<dim3(DM / 32, MLPD / 32, NEXP), dim3(32, 8)>>>(w2, w2t, MLPD, DM);
    }
    router_kernel<<<(NTOK_DET * 32 + 255) / 256, 256>>>(xdet, 0, NTOK_DET, 0);
    router_kernel<<<(NTOK_CLS * 32 + 255) / 256, 256>>>(xcls, 1, NTOK_CLS, NTOK_DET);
    positions_kernel<<<8, 256>>>(1024, CAP_DET, 0, 0);
    positions_kernel<<<8, 256>>>(128, CAP_CLS, NTOK_DET, 2048);
    gather_kernel<<<MTOT, 192>>>(xdet, xcls);
    gemm1_tc<<<dim3(MLPD / 128, MTOT / 128), 128, SMEM_DYN>>>(b1);
    gemm2_tc<<<dim3(DM / 128, MTOT / 128), 128, SMEM_DYN>>>(b2);
    scatter_kernel<<<NTOK, 192>>>(out);
}

// round 8
// speedup vs baseline: 1.0900x; 1.0900x over previous
#include <cuda_runtime.h>
#include <cuda_fp16.h>
#include <math.h>
#include <stdint.h>

// ---------------------------------------------------------------------------
// MoE block via mma.sync fp16 (fp32 accum). R5 config (256 thr, 64x32 warp
// tiles) + K-major B with ldmatrix.trans (no weight transpose) + 3-stage
// cp.async pipeline. tcgen05 unavailable (toolchain targets sm_103).
// ---------------------------------------------------------------------------

#define NEXP 8
#define DM 768
#define MLPD 3072
#define CAP_DET 256
#define CAP_CLS 32
#define RPE 2304
#define MTOT (NEXP * RPE)
#define NTOK_DET 8192
#define NTOK_CLS 1024
#define NTOK (NTOK_DET + NTOK_CLS)

#define CHUNK 64                         // K halves per pipeline stage
#define ASTR 72                          // A smem row stride (halves)
#define BSTR 136                         // B smem row stride (halves), 17x16B
#define A_HALVES (128 * ASTR)            // 9216
#define B_HALVES (CHUNK * BSTR)          // 8704
#define STAGE_HALVES (A_HALVES + B_HALVES)
#define NBUF 3
#define SMEM_DYN (NBUF * STAGE_HALVES * 2)   // 107520 bytes

// --------------------------- scratch ---------------------------------------
__device__ __half g_xg[(size_t)MTOT * DM];
__device__ __half g_h [(size_t)MTOT * MLPD];
__device__ __half g_ye[(size_t)MTOT * DM];
__device__ __half g_w1h[(size_t)NEXP * DM * MLPD];   // [E, K=768,  N=3072]
__device__ __half g_w2h[(size_t)NEXP * MLPD * DM];   // [E, K=3072, N=768]
__device__ float  g_wrt[2][NEXP * DM];
__device__ int    g_row_src[MTOT];
__device__ signed char g_tok_e[NTOK][2];
__device__ float  g_tok_p[NTOK][2];
__device__ int    g_tok_rows[NTOK][2];
__device__ float  g_tok_g[NTOK][2];

// --------------------------- helpers ---------------------------------------
__device__ __forceinline__ uint32_t smem_u32(const void* p) {
    uint32_t a;
    asm("{ .reg .u64 t; cvta.to.shared.u64 t, %1; cvt.u32.u64 %0, t; }"
        : "=r"(a) : "l"(p));
    return a;
}
__device__ __forceinline__ void cp_async16(uint32_t sdst, const void* gsrc) {
    asm volatile("cp.async.cg.shared.global [%0], [%1], 16;"
                 :: "r"(sdst), "l"(gsrc) : "memory");
}
__device__ __forceinline__ void cp_commit() {
    asm volatile("cp.async.commit_group;" ::: "memory");
}
template<int N>
__device__ __forceinline__ void cp_wait() {
    asm volatile("cp.async.wait_group %0;" :: "n"(N) : "memory");
}
__device__ __forceinline__ void ldsm_x4(uint32_t* r, uint32_t addr) {
    asm volatile("ldmatrix.sync.aligned.m8n8.x4.shared.b16 {%0,%1,%2,%3}, [%4];"
                 : "=r"(r[0]), "=r"(r[1]), "=r"(r[2]), "=r"(r[3]) : "r"(addr));
}
__device__ __forceinline__ void ldsm_x4_trans(uint32_t* r, uint32_t addr) {
    asm volatile("ldmatrix.sync.aligned.m8n8.x4.trans.shared.b16 {%0,%1,%2,%3}, [%4];"
                 : "=r"(r[0]), "=r"(r[1]), "=r"(r[2]), "=r"(r[3]) : "r"(addr));
}
__device__ __forceinline__ void mma_f16(float* d, const uint32_t* a,
                                        const uint32_t* b) {
    asm volatile(
        "mma.sync.aligned.m16n8k16.row.col.f32.f16.f16.f32 "
        "{%0,%1,%2,%3}, {%4,%5,%6,%7}, {%8,%9}, {%0,%1,%2,%3};"
        : "+f"(d[0]), "+f"(d[1]), "+f"(d[2]), "+f"(d[3])
        : "r"(a[0]), "r"(a[1]), "r"(a[2]), "r"(a[3]),
          "r"(b[0]), "r"(b[1]));
}
__device__ __forceinline__ float gelu_tanh(float x) {
    float x3 = x * x * x;
    return 0.5f * x * (1.0f + tanhf(0.7978845608028654f * (x + 0.044715f * x3)));
}

// --------------------------- init ------------------------------------------
__global__ void init_kernel() {
    int i = blockIdx.x * blockDim.x + threadIdx.x;
    if (i < MTOT) g_row_src[i] = -1;
    if (i < NTOK * 2) {
        ((int*)g_tok_rows)[i] = -1;
        ((float*)g_tok_g)[i] = 0.0f;
    }
}

// --------------- weight convert fp32 -> half (layout preserved) -------------
__global__ void convert_kernel(const float* __restrict__ w1,
                               const float* __restrict__ w2) {
    const int n1 = NEXP * DM * MLPD / 4;     // float4 count per tensor
    int i = blockIdx.x * blockDim.x + threadIdx.x;
    int stride = gridDim.x * blockDim.x;
    for (; i < 2 * n1; i += stride) {
        if (i < n1) {
            float4 v = ((const float4*)w1)[i];
            __half2* d = (__half2*)g_w1h + i * 2;
            d[0] = __floats2half2_rn(v.x, v.y);
            d[1] = __floats2half2_rn(v.z, v.w);
        } else {
            int j = i - n1;
            float4 v = ((const float4*)w2)[j];
            __half2* d = (__half2*)g_w2h + j * 2;
            d[0] = __floats2half2_rn(v.x, v.y);
            d[1] = __floats2half2_rn(v.z, v.w);
        }
    }
}

// ----------------- router weight transpose [D,E] -> [E,D] -------------------
__global__ void wr_transpose_kernel(const float* __restrict__ wr0,
                                    const float* __restrict__ wr1) {
    int i = blockIdx.x * blockDim.x + threadIdx.x;
    if (i >= DM * NEXP) return;
    int d = i / NEXP, e = i % NEXP;
    g_wrt[0][e * DM + d] = wr0[i];
    g_wrt[1][e * DM + d] = wr1[i];
}

// --------------------------- router ----------------------------------------
__global__ void router_kernel(const float* __restrict__ x,
                              int which, int n_tokens, int tok_base) {
    int gwarp = (blockIdx.x * blockDim.x + threadIdx.x) >> 5;
    int lane  = threadIdx.x & 31;
    if (gwarp >= n_tokens) return;
    const float4* xr = (const float4*)(x + (size_t)gwarp * DM);
    const float* wt = g_wrt[which];

    float acc[NEXP];
#pragma unroll
    for (int e = 0; e < NEXP; e++) acc[e] = 0.f;
#pragma unroll
    for (int it = 0; it < 6; it++) {
        int d4 = it * 32 + lane;
        float4 xv = xr[d4];
#pragma unroll
        for (int e = 0; e < NEXP; e++) {
            float4 wv = ((const float4*)(wt + e * DM))[d4];
            acc[e] += xv.x * wv.x + xv.y * wv.y + xv.z * wv.z + xv.w * wv.w;
        }
    }
#pragma unroll
    for (int e = 0; e < NEXP; e++) {
#pragma unroll
        for (int off = 16; off > 0; off >>= 1)
            acc[e] += __shfl_xor_sync(0xffffffffu, acc[e], off);
    }
    if (lane == 0) {
        float mx = acc[0];
#pragma unroll
        for (int e = 1; e < NEXP; e++) mx = fmaxf(mx, acc[e]);
        float p[NEXP]; float s = 0.f;
#pragma unroll
        for (int e = 0; e < NEXP; e++) { p[e] = expf(acc[e] - mx); s += p[e]; }
        float inv = 1.0f / s;
        int e0 = 0;
#pragma unroll
        for (int e = 1; e < NEXP; e++) if (p[e] > p[e0]) e0 = e;
        int e1 = (e0 == 0) ? 1 : 0;
#pragma unroll
        for (int e = 0; e < NEXP; e++) if (e != e0 && p[e] > p[e1]) e1 = e;
        int t = tok_base + gwarp;
        g_tok_e[t][0] = (signed char)e0;
        g_tok_e[t][1] = (signed char)e1;
        g_tok_p[t][0] = p[e0] * inv;
        g_tok_p[t][1] = p[e1] * inv;
    }
}

// ------------------ positions (rank-major cumsum + capacity) ----------------
__global__ void positions_kernel(int S, int C, int tok_base, int row_off) {
    __shared__ signed char se0[1024], se1[1024];
    __shared__ float sg0[1024], sg1[1024];
    int g = blockIdx.x;
    int tid = threadIdx.x;
    for (int t = tid; t < S; t += blockDim.x) {
        int gt = tok_base + g * S + t;
        se0[t] = g_tok_e[gt][0];
        se1[t] = g_tok_e[gt][1];
        sg0[t] = g_tok_p[gt][0];
        sg1[t] = g_tok_p[gt][1];
    }
    __syncthreads();
    int e = tid >> 5;
    int lane = tid & 31;
    int base = 0;
    int total = 2 * S;
    for (int j0 = 0; j0 < total; j0 += 32) {
        int j = j0 + lane;
        int exp_j = -1;
        if (j < total) exp_j = (j < S) ? (int)se0[j] : (int)se1[j - S];
        bool m = (exp_j == e);
        unsigned mask = __ballot_sync(0xffffffffu, m);
        if (m) {
            int pos = base + __popc(mask & ((1u << lane) - 1u));
            if (pos < C) {
                int t = (j < S) ? j : (j - S);
                int r = (j < S) ? 0 : 1;
                int gt = tok_base + g * S + t;
                float gate = (r == 0) ? sg0[t] : sg1[t];
                int row = e * RPE + row_off + g * C + pos;
                g_row_src[row] = gt;
                g_tok_rows[gt][r] = row;
                g_tok_g[gt][r] = gate;
            }
        }
        base += __popc(mask);
    }
}

// --------------------------- gather (fp32 -> half) ---------------------------
__global__ void gather_kernel(const float* __restrict__ xdet,
                              const float* __restrict__ xcls) {
    int row = blockIdx.x;
    int i = threadIdx.x;
    int src = g_row_src[row];
    __half2 h0 = __half2half2(__float2half_rn(0.f));
    __half2 h1 = h0;
    if (src >= 0) {
        const float* xp = (src < NTOK_DET)
            ? (xdet + (size_t)src * DM)
            : (xcls + (size_t)(src - NTOK_DET) * DM);
        float4 v = ((const float4*)xp)[i];
        h0 = __floats2half2_rn(v.x, v.y);
        h1 = __floats2half2_rn(v.z, v.w);
    }
    __half2* dst = (__half2*)(g_xg + (size_t)row * DM) + i * 2;
    dst[0] = h0;
    dst[1] = h1;
}

// --------------------------- mma.sync fp16 GEMM ------------------------------
// C[M,N] = A[M,K] * W[e][K,N]  (+bias fp32, optional GELU)
// 128x128 CTA tile, 256 threads (2 M-warps x 4 N-warps, 64x32 per warp).
// A tile [m][k] (ASTR), B tile [k][n] (BSTR) with ldmatrix.trans fragments.
// 3-stage cp.async pipeline.
template<int K, int NTOT, bool GELU>
__device__ __forceinline__ void tc_gemm(const __half* __restrict__ A,
                                        const __half* __restrict__ W,
                                        const float* __restrict__ bias,
                                        __half* __restrict__ C) {
    extern __shared__ __half smem[];
    int tid = threadIdx.x;
    int wid = tid >> 5, lane = tid & 31;
    int gid = lane >> 2, tig = lane & 3;
    int warp_m = wid & 1, warp_n = wid >> 1;
    int m_base = warp_m * 64, n_base = warp_n * 32;
    int bx = blockIdx.x, by = blockIdx.y;
    int e = (by * 128) / RPE;
    const __half* Ab = A + (size_t)by * 128 * K;
    const __half* Wb = W + (size_t)e * K * NTOT + (size_t)bx * 128;

    // A ldmatrix offsets (non-trans): rows m, k segments
    uint32_t a_off = (uint32_t)((m_base + (lane & 15)) * ASTR + ((lane >> 4) << 3));
    // B ldmatrix offsets (trans): lane groups q=lane>>3:
    //   k-off = (q&1)*8 + (lane&7), n-off = (q>>1)*8
    {
    }
    uint32_t b_off = (uint32_t)((((lane >> 3) & 1) * 8 + (lane & 7)) * BSTR
                                + n_base + ((lane >> 4) << 3));

    float acc[4][4][4];
#pragma unroll
    for (int mi = 0; mi < 4; mi++)
#pragma unroll
        for (int ni = 0; ni < 4; ni++)
#pragma unroll
            for (int q = 0; q < 4; q++) acc[mi][ni][q] = 0.f;

    const int NC = K / CHUNK;
    uint32_t sbase = smem_u32(smem);

    auto issue_stage = [&](int c) {
        int buf = c % NBUF;
        uint32_t as = sbase + (uint32_t)(buf * STAGE_HALVES) * 2u;
        uint32_t bs = as + (uint32_t)A_HALVES * 2u;
        int kc = c * CHUNK;
        // A: 128 rows x 64 halves = 1024 x 16B
#pragma unroll
        for (int j = 0; j < 4; j++) {
            int idx = j * 256 + tid;
            int row = idx >> 3, seg = idx & 7;
            cp_async16(as + (uint32_t)(row * ASTR + seg * 8) * 2u,
                       Ab + (size_t)row * K + kc + seg * 8);
        }
        // B: 64 k-rows x 128 n-halves = 1024 x 16B
#pragma unroll
        for (int j = 0; j < 4; j++) {
            int idx = j * 256 + tid;
            int row = idx >> 4, seg = idx & 15;
            cp_async16(bs + (uint32_t)(row * BSTR + seg * 8) * 2u,
                       Wb + (size_t)(kc + row) * NTOT + seg * 8);
        }
        cp_commit();
    };

    issue_stage(0);
    if (NC > 1) issue_stage(1);
    for (int c = 0; c < NC; c++) {
        if (c + 2 < NC) { issue_stage(c + 2); cp_wait<2>(); }
        else if (c + 1 < NC) { cp_wait<1>(); }
        else { cp_wait<0>(); }
        __syncthreads();

        uint32_t as = sbase + (uint32_t)((c % NBUF) * STAGE_HALVES) * 2u;
        uint32_t bs = as + (uint32_t)A_HALVES * 2u;
        uint32_t a_base = as + a_off * 2u;
        uint32_t b_base = bs + b_off * 2u;
#pragma unroll
        for (int kk = 0; kk < CHUNK; kk += 16) {
            uint32_t afr[4][4];
#pragma unroll
            for (int mi = 0; mi < 4; mi++)
                ldsm_x4(afr[mi], a_base + (uint32_t)(mi * 16 * ASTR + kk) * 2u);
            uint32_t bfr[2][4];
#pragma unroll
            for (int p = 0; p < 2; p++)
                ldsm_x4_trans(bfr[p], b_base + (uint32_t)(kk * BSTR + p * 16) * 2u);
#pragma unroll
            for (int mi = 0; mi < 4; mi++)
#pragma unroll
                for (int ni = 0; ni < 4; ni++)
                    mma_f16(acc[mi][ni], afr[mi], &bfr[ni >> 1][(ni & 1) * 2]);
        }
        __syncthreads();
    }

#pragma unroll
    for (int ni = 0; ni < 4; ni++) {
        int cb = bx * 128 + n_base + ni * 8 + 2 * tig;
        float b0 = bias[e * NTOT + cb];
        float b1 = bias[e * NTOT + cb + 1];
#pragma unroll
        for (int mi = 0; mi < 4; mi++) {
            int r0 = by * 128 + m_base + mi * 16 + gid;
            float v0 = acc[mi][ni][0] + b0;
            float v1 = acc[mi][ni][1] + b1;
            float v2 = acc[mi][ni][2] + b0;
            float v3 = acc[mi][ni][3] + b1;
            if (GELU) {
                v0 = gelu_tanh(v0); v1 = gelu_tanh(v1);
                v2 = gelu_tanh(v2); v3 = gelu_tanh(v3);
            }
            *(__half2*)(C + (size_t)r0 * NTOT + cb)       = __floats2half2_rn(v0, v1);
            *(__half2*)(C + (size_t)(r0 + 8) * NTOT + cb) = __floats2half2_rn(v2, v3);
        }
    }
}

__global__ __launch_bounds__(256, 2)
void gemm1_tc(const float* __restrict__ b1) {
    tc_gemm<DM, MLPD, true>(g_xg, g_w1h, b1, g_h);
}
__global__ __launch_bounds__(256, 2)
void gemm2_tc(const float* __restrict__ b2) {
    tc_gemm<MLPD, DM, false>(g_h, g_w2h, b2, g_ye);
}

// --------------------------- scatter ----------------------------------------
__global__ void scatter_kernel(float* __restrict__ out) {
    int t = blockIdx.x;
    int i = threadIdx.x;                 // 192 threads, 4 elems each
    int r0 = g_tok_rows[t][0];
    int r1 = g_tok_rows[t][1];
    float ga = g_tok_g[t][0];
    float gb = g_tok_g[t][1];
    float4 acc = make_float4(0.f, 0.f, 0.f, 0.f);
    if (r0 >= 0) {
        const __half2* p = (const __half2*)(g_ye + (size_t)r0 * DM) + i * 2;
        float2 u = __half22float2(p[0]);
        float2 v = __half22float2(p[1]);
        acc.x = ga * u.x; acc.y = ga * u.y; acc.z = ga * v.x; acc.w = ga * v.y;
    }
    if (r1 >= 0) {
        const __half2* p = (const __half2*)(g_ye + (size_t)r1 * DM) + i * 2;
        float2 u = __half22float2(p[0]);
        float2 v = __half22float2(p[1]);
        acc.x += gb * u.x; acc.y += gb * u.y; acc.z += gb * v.x; acc.w += gb * v.y;
    }
    ((float4*)(out + (size_t)t * DM))[i] = acc;
}

// --------------------------- launch -----------------------------------------
extern "C" void kernel_launch(void* const* d_in, const int* in_sizes, int n_in,
                              void* d_out, int out_size) {
    (void)in_sizes; (void)n_in; (void)out_size;
    const float* xdet = (const float*)d_in[0];
    const float* xcls = (const float*)d_in[1];
    const float* wrd  = (const float*)d_in[2];
    const float* wrc  = (const float*)d_in[3];
    const float* w1   = (const float*)d_in[4];
    const float* b1   = (const float*)d_in[5];
    const float* w2   = (const float*)d_in[6];
    const float* b2   = (const float*)d_in[7];
    float* out = (float*)d_out;

    cudaFuncSetAttribute(gemm1_tc, cudaFuncAttributeMaxDynamicSharedMemorySize, SMEM_DYN);
    cudaFuncSetAttribute(gemm2_tc, cudaFuncAttributeMaxDynamicSharedMemorySize, SMEM_DYN);

    init_kernel<<<(MTOT + 255) / 256, 256>>>();
    convert_kernel<<<4096, 256>>>(w1, w2);
    wr_transpose_kernel<<<(DM * NEXP + 255) / 256, 256>>>(wrd, wrc);
    router_kernel<<<(NTOK_DET * 32 + 255) / 256, 256>>>(xdet, 0, NTOK_DET, 0);
    router_kernel<<<(NTOK_CLS * 32 + 255) / 256, 256>>>(xcls, 1, NTOK_CLS, NTOK_DET);
    positions_kernel<<<8, 256>>>(1024, CAP_DET, 0, 0);
    positions_kernel<<<8, 256>>>(128, CAP_CLS, NTOK_DET, 2048);
    gather_kernel<<<MTOT, 192>>>(xdet, xcls);
    gemm1_tc<<<dim3(MLPD / 128, MTOT / 128), 256, SMEM_DYN>>>(b1);
    gemm2_tc<<<dim3(DM / 128, MTOT / 128), 256, SMEM_DYN>>>(b2);
    scatter_kernel<<<NTOK, 192>>>(out);
}

// round 9
// speedup vs baseline: 1.1202x; 1.0277x over previous
#include <cuda_runtime.h>
#include <cuda_fp16.h>
#include <math.h>
#include <stdint.h>

// ---------------------------------------------------------------------------
// MoE block via mma.sync fp16 (fp32 accum), ldmatrix(.trans), 3-stage
// cp.async pipeline, fused scatter epilogue. 6 launches total.
// tcgen05 unavailable (toolchain assembles for .target sm_103).
// ---------------------------------------------------------------------------

#define NEXP 8
#define DM 768
#define MLPD 3072
#define CAP_DET 256
#define CAP_CLS 32
#define RPE 2304
#define MTOT (NEXP * RPE)
#define NTOK_DET 8192
#define NTOK_CLS 1024
#define NTOK (NTOK_DET + NTOK_CLS)

#define CHUNK 64
#define ASTR 72
#define BSTR 136
#define A_HALVES (128 * ASTR)
#define B_HALVES (CHUNK * BSTR)
#define STAGE_HALVES (A_HALVES + B_HALVES)
#define NBUF 3
#define SMEM_DYN (NBUF * STAGE_HALVES * 2)   // 107520 bytes

// --------------------------- scratch ---------------------------------------
__device__ __half g_xg[(size_t)MTOT * DM];
__device__ __half g_h [(size_t)MTOT * MLPD];
__device__ __half g_w1h[(size_t)NEXP * DM * MLPD];   // [E, K=768,  N=3072]
__device__ __half g_w2h[(size_t)NEXP * MLPD * DM];   // [E, K=3072, N=768]
__device__ float  g_wrt[2][NEXP * DM];
__device__ int    g_row_src[MTOT];
__device__ float  g_row_gate[MTOT];
__device__ signed char g_tok_e[NTOK][2];
__device__ float  g_tok_p[NTOK][2];

// --------------------------- helpers ---------------------------------------
__device__ __forceinline__ uint32_t smem_u32(const void* p) {
    uint32_t a;
    asm("{ .reg .u64 t; cvta.to.shared.u64 t, %1; cvt.u32.u64 %0, t; }"
        : "=r"(a) : "l"(p));
    return a;
}
__device__ __forceinline__ void cp_async16(uint32_t sdst, const void* gsrc) {
    asm volatile("cp.async.cg.shared.global [%0], [%1], 16;"
                 :: "r"(sdst), "l"(gsrc) : "memory");
}
__device__ __forceinline__ void cp_commit() {
    asm volatile("cp.async.commit_group;" ::: "memory");
}
template<int N>
__device__ __forceinline__ void cp_wait() {
    asm volatile("cp.async.wait_group %0;" :: "n"(N) : "memory");
}
__device__ __forceinline__ void ldsm_x4(uint32_t* r, uint32_t addr) {
    asm volatile("ldmatrix.sync.aligned.m8n8.x4.shared.b16 {%0,%1,%2,%3}, [%4];"
                 : "=r"(r[0]), "=r"(r[1]), "=r"(r[2]), "=r"(r[3]) : "r"(addr));
}
__device__ __forceinline__ void ldsm_x4_trans(uint32_t* r, uint32_t addr) {
    asm volatile("ldmatrix.sync.aligned.m8n8.x4.trans.shared.b16 {%0,%1,%2,%3}, [%4];"
                 : "=r"(r[0]), "=r"(r[1]), "=r"(r[2]), "=r"(r[3]) : "r"(addr));
}
__device__ __forceinline__ void mma_f16(float* d, const uint32_t* a,
                                        const uint32_t* b) {
    asm volatile(
        "mma.sync.aligned.m16n8k16.row.col.f32.f16.f16.f32 "
        "{%0,%1,%2,%3}, {%4,%5,%6,%7}, {%8,%9}, {%0,%1,%2,%3};"
        : "+f"(d[0]), "+f"(d[1]), "+f"(d[2]), "+f"(d[3])
        : "r"(a[0]), "r"(a[1]), "r"(a[2]), "r"(a[3]),
          "r"(b[0]), "r"(b[1]));
}
__device__ __forceinline__ float gelu_tanh(float x) {
    float x3 = x * x * x;
    return 0.5f * x * (1.0f + tanhf(0.7978845608028654f * (x + 0.044715f * x3)));
}

// ------------------- prep: zero out, init, transpose, convert ---------------
#define PREP_OUT4   (NTOK * DM / 4)                 // 1769472 float4 (zero out)
#define PREP_SRC    (MTOT)                          // 18432 ints
#define PREP_WRT    (DM * NEXP)                     // 6144
#define PREP_W4     (NEXP * DM * MLPD / 4)          // 4718592 float4 each
#define PREP_TOTAL  (PREP_OUT4 + PREP_SRC + PREP_WRT + 2 * PREP_W4)

__global__ void prep_kernel(float* __restrict__ out,
                            const float* __restrict__ wr0,
                            const float* __restrict__ wr1,
                            const float* __restrict__ w1,
                            const float* __restrict__ w2) {
    int stride = gridDim.x * blockDim.x;
    for (long long i = blockIdx.x * blockDim.x + threadIdx.x; i < PREP_TOTAL; i += stride) {
        if (i < PREP_OUT4) {
            ((float4*)out)[i] = make_float4(0.f, 0.f, 0.f, 0.f);
        } else if (i < PREP_OUT4 + PREP_SRC) {
            g_row_src[i - PREP_OUT4] = -1;
        } else if (i < PREP_OUT4 + PREP_SRC + PREP_WRT) {
            int j = (int)(i - PREP_OUT4 - PREP_SRC);
            int d = j / NEXP, e = j % NEXP;
            g_wrt[0][e * DM + d] = wr0[j];
            g_wrt[1][e * DM + d] = wr1[j];
        } else if (i < PREP_OUT4 + PREP_SRC + PREP_WRT + PREP_W4) {
            long long j = i - (PREP_OUT4 + PREP_SRC + PREP_WRT);
            float4 v = ((const float4*)w1)[j];
            __half2* d = (__half2*)g_w1h + j * 2;
            d[0] = __floats2half2_rn(v.x, v.y);
            d[1] = __floats2half2_rn(v.z, v.w);
        } else {
            long long j = i - (PREP_OUT4 + PREP_SRC + PREP_WRT + PREP_W4);
            float4 v = ((const float4*)w2)[j];
            __half2* d = (__half2*)g_w2h + j * 2;
            d[0] = __floats2half2_rn(v.x, v.y);
            d[1] = __floats2half2_rn(v.z, v.w);
        }
    }
}

// --------------------------- router (merged, smem weights) -------------------
// 8 tokens per block (one warp each); blocks 0..1023 det, 1024..1151 cls.
__global__ __launch_bounds__(256)
void router_kernel(const float* __restrict__ xdet,
                   const float* __restrict__ xcls) {
    __shared__ float sw[NEXP * DM];
    int b = blockIdx.x;
    int tid = threadIdx.x;
    int which = (b < NTOK_DET / 8) ? 0 : 1;
    // load this stream's router weights (24KB) into smem
    const float4* wsrc = (const float4*)g_wrt[which];
#pragma unroll
    for (int j = 0; j < 6; j++)
        ((float4*)sw)[j * 256 + tid] = wsrc[j * 256 + tid];
    __syncthreads();

    int wid = tid >> 5, lane = tid & 31;
    int t = b * 8 + wid;                       // global token id
    const float* xp = (t < NTOK_DET)
        ? (xdet + (size_t)t * DM)
        : (xcls + (size_t)(t - NTOK_DET) * DM);
    const float4* xr = (const float4*)xp;

    float acc[NEXP];
#pragma unroll
    for (int e = 0; e < NEXP; e++) acc[e] = 0.f;
#pragma unroll
    for (int it = 0; it < 6; it++) {
        int d4 = it * 32 + lane;
        float4 xv = xr[d4];
#pragma unroll
        for (int e = 0; e < NEXP; e++) {
            float4 wv = ((const float4*)(sw + e * DM))[d4];
            acc[e] += xv.x * wv.x + xv.y * wv.y + xv.z * wv.z + xv.w * wv.w;
        }
    }
#pragma unroll
    for (int e = 0; e < NEXP; e++) {
#pragma unroll
        for (int off = 16; off > 0; off >>= 1)
            acc[e] += __shfl_xor_sync(0xffffffffu, acc[e], off);
    }
    if (lane == 0) {
        float mx = acc[0];
#pragma unroll
        for (int e = 1; e < NEXP; e++) mx = fmaxf(mx, acc[e]);
        float p[NEXP]; float s = 0.f;
#pragma unroll
        for (int e = 0; e < NEXP; e++) { p[e] = expf(acc[e] - mx); s += p[e]; }
        float inv = 1.0f / s;
        int e0 = 0;
#pragma unroll
        for (int e = 1; e < NEXP; e++) if (p[e] > p[e0]) e0 = e;
        int e1 = (e0 == 0) ? 1 : 0;
#pragma unroll
        for (int e = 0; e < NEXP; e++) if (e != e0 && p[e] > p[e1]) e1 = e;
        g_tok_e[t][0] = (signed char)e0;
        g_tok_e[t][1] = (signed char)e1;
        g_tok_p[t][0] = p[e0] * inv;
        g_tok_p[t][1] = p[e1] * inv;
    }
}

// ------------------ positions (merged det+cls, grid 16) ----------------------
__global__ void positions_kernel() {
    __shared__ signed char se0[1024], se1[1024];
    __shared__ float sg0[1024], sg1[1024];
    int blk = blockIdx.x;
    int det = (blk < 8);
    int g = det ? blk : blk - 8;
    int S = det ? 1024 : 128;
    int C = det ? CAP_DET : CAP_CLS;
    int tok_base = det ? 0 : NTOK_DET;
    int row_off = det ? 0 : 2048;
    int tid = threadIdx.x;
    for (int t = tid; t < S; t += blockDim.x) {
        int gt = tok_base + g * S + t;
        se0[t] = g_tok_e[gt][0];
        se1[t] = g_tok_e[gt][1];
        sg0[t] = g_tok_p[gt][0];
        sg1[t] = g_tok_p[gt][1];
    }
    __syncthreads();
    int e = tid >> 5;
    int lane = tid & 31;
    int base = 0;
    int total = 2 * S;
    for (int j0 = 0; j0 < total; j0 += 32) {
        int j = j0 + lane;
        int exp_j = -1;
        if (j < total) exp_j = (j < S) ? (int)se0[j] : (int)se1[j - S];
        bool m = (exp_j == e);
        unsigned mask = __ballot_sync(0xffffffffu, m);
        if (m) {
            int pos = base + __popc(mask & ((1u << lane) - 1u));
            if (pos < C) {
                int t = (j < S) ? j : (j - S);
                int gt = tok_base + g * S + t;
                float gate = (j < S) ? sg0[t] : sg1[t];
                int row = e * RPE + row_off + g * C + pos;
                g_row_src[row] = gt;
                g_row_gate[row] = gate;
            }
        }
        base += __popc(mask);
    }
}

// --------------------------- gather (fp32 -> half) ---------------------------
__global__ void gather_kernel(const float* __restrict__ xdet,
                              const float* __restrict__ xcls) {
    int row = blockIdx.x;
    int i = threadIdx.x;
    int src = g_row_src[row];
    __half2 h0 = __half2half2(__float2half_rn(0.f));
    __half2 h1 = h0;
    if (src >= 0) {
        const float* xp = (src < NTOK_DET)
            ? (xdet + (size_t)src * DM)
            : (xcls + (size_t)(src - NTOK_DET) * DM);
        float4 v = ((const float4*)xp)[i];
        h0 = __floats2half2_rn(v.x, v.y);
        h1 = __floats2half2_rn(v.z, v.w);
    }
    __half2* dst = (__half2*)(g_xg + (size_t)row * DM) + i * 2;
    dst[0] = h0;
    dst[1] = h1;
}

// --------------------------- mma.sync fp16 GEMM ------------------------------
// FUSE=false: C[M,N] = gelu(A*W + b) stored half (GEMM1)
// FUSE=true : out[src(row)] += gate(row) * (A*W + b)   (GEMM2 + scatter)
template<int K, int NTOT, bool FUSE>
__device__ __forceinline__ void tc_gemm(const __half* __restrict__ A,
                                        const __half* __restrict__ W,
                                        const float* __restrict__ bias,
                                        __half* __restrict__ C,
                                        float* __restrict__ out) {
    extern __shared__ __half smem[];
    int tid = threadIdx.x;
    int wid = tid >> 5, lane = tid & 31;
    int gid = lane >> 2, tig = lane & 3;
    int warp_m = wid & 1, warp_n = wid >> 1;
    int m_base = warp_m * 64, n_base = warp_n * 32;
    int bx = blockIdx.x, by = blockIdx.y;
    int e = (by * 128) / RPE;
    const __half* Ab = A + (size_t)by * 128 * K;
    const __half* Wb = W + (size_t)e * K * NTOT + (size_t)bx * 128;

    uint32_t a_off = (uint32_t)((m_base + (lane & 15)) * ASTR + ((lane >> 4) << 3));
    uint32_t b_off = (uint32_t)((((lane >> 3) & 1) * 8 + (lane & 7)) * BSTR
                                + n_base + ((lane >> 4) << 3));

    float acc[4][4][4];
#pragma unroll
    for (int mi = 0; mi < 4; mi++)
#pragma unroll
        for (int ni = 0; ni < 4; ni++)
#pragma unroll
            for (int q = 0; q < 4; q++) acc[mi][ni][q] = 0.f;

    const int NC = K / CHUNK;
    uint32_t sbase = smem_u32(smem);

    auto issue_stage = [&](int c) {
        int buf = c % NBUF;
        uint32_t as = sbase + (uint32_t)(buf * STAGE_HALVES) * 2u;
        uint32_t bs = as + (uint32_t)A_HALVES * 2u;
        int kc = c * CHUNK;
#pragma unroll
        for (int j = 0; j < 4; j++) {
            int idx = j * 256 + tid;
            int row = idx >> 3, seg = idx & 7;
            cp_async16(as + (uint32_t)(row * ASTR + seg * 8) * 2u,
                       Ab + (size_t)row * K + kc + seg * 8);
        }
#pragma unroll
        for (int j = 0; j < 4; j++) {
            int idx = j * 256 + tid;
            int row = idx >> 4, seg = idx & 15;
            cp_async16(bs + (uint32_t)(row * BSTR + seg * 8) * 2u,
                       Wb + (size_t)(kc + row) * NTOT + seg * 8);
        }
        cp_commit();
    };

    issue_stage(0);
    if (NC > 1) issue_stage(1);
    for (int c = 0; c < NC; c++) {
        if (c + 2 < NC) { issue_stage(c + 2); cp_wait<2>(); }
        else if (c + 1 < NC) { cp_wait<1>(); }
        else { cp_wait<0>(); }
        __syncthreads();

        uint32_t as = sbase + (uint32_t)((c % NBUF) * STAGE_HALVES) * 2u;
        uint32_t bs = as + (uint32_t)A_HALVES * 2u;
        uint32_t a_base = as + a_off * 2u;
        uint32_t b_base = bs + b_off * 2u;
#pragma unroll
        for (int kk = 0; kk < CHUNK; kk += 16) {
            uint32_t afr[4][4];
#pragma unroll
            for (int mi = 0; mi < 4; mi++)
                ldsm_x4(afr[mi], a_base + (uint32_t)(mi * 16 * ASTR + kk) * 2u);
            uint32_t bfr[2][4];
#pragma unroll
            for (int p = 0; p < 2; p++)
                ldsm_x4_trans(bfr[p], b_base + (uint32_t)(kk * BSTR + p * 16) * 2u);
#pragma unroll
            for (int mi = 0; mi < 4; mi++)
#pragma unroll
                for (int ni = 0; ni < 4; ni++)
                    mma_f16(acc[mi][ni], afr[mi], &bfr[ni >> 1][(ni & 1) * 2]);
        }
        __syncthreads();
    }

    if (!FUSE) {
        // GEMM1 epilogue: bias + GELU -> half store
#pragma unroll
        for (int ni = 0; ni < 4; ni++) {
            int cb = bx * 128 + n_base + ni * 8 + 2 * tig;
            float b0 = bias[e * NTOT + cb];
            float b1 = bias[e * NTOT + cb + 1];
#pragma unroll
            for (int mi = 0; mi < 4; mi++) {
                int r0 = by * 128 + m_base + mi * 16 + gid;
                float v0 = gelu_tanh(acc[mi][ni][0] + b0);
                float v1 = gelu_tanh(acc[mi][ni][1] + b1);
                float v2 = gelu_tanh(acc[mi][ni][2] + b0);
                float v3 = gelu_tanh(acc[mi][ni][3] + b1);
                *(__half2*)(C + (size_t)r0 * NTOT + cb)       = __floats2half2_rn(v0, v1);
                *(__half2*)(C + (size_t)(r0 + 8) * NTOT + cb) = __floats2half2_rn(v2, v3);
            }
        }
    } else {
        // GEMM2 fused scatter epilogue: out[src] += gate * (acc + bias)
#pragma unroll
        for (int mi = 0; mi < 4; mi++) {
            int r0 = by * 128 + m_base + mi * 16 + gid;
            int src0 = __ldg(&g_row_src[r0]);
            int src1 = __ldg(&g_row_src[r0 + 8]);
            float gt0 = src0 >= 0 ? __ldg(&g_row_gate[r0]) : 0.f;
            float gt1 = src1 >= 0 ? __ldg(&g_row_gate[r0 + 8]) : 0.f;
#pragma unroll
            for (int ni = 0; ni < 4; ni++) {
                int cb = bx * 128 + n_base + ni * 8 + 2 * tig;
                float b0 = bias[e * NTOT + cb];
                float b1 = bias[e * NTOT + cb + 1];
                if (src0 >= 0) {
                    atomicAdd(out + (size_t)src0 * DM + cb,     gt0 * (acc[mi][ni][0] + b0));
                    atomicAdd(out + (size_t)src0 * DM + cb + 1, gt0 * (acc[mi][ni][1] + b1));
                }
                if (src1 >= 0) {
                    atomicAdd(out + (size_t)src1 * DM + cb,     gt1 * (acc[mi][ni][2] + b0));
                    atomicAdd(out + (size_t)src1 * DM + cb + 1, gt1 * (acc[mi][ni][3] + b1));
                }
            }
        }
    }
}

__global__ __launch_bounds__(256, 2)
void gemm1_tc(const float* __restrict__ b1) {
    tc_gemm<DM, MLPD, false>(g_xg, g_w1h, b1, g_h, nullptr);
}
__global__ __launch_bounds__(256, 2)
void gemm2_tc(const float* __restrict__ b2, float* __restrict__ out) {
    tc_gemm<MLPD, DM, true>(g_h, g_w2h, b2, nullptr, out);
}

// --------------------------- launch -----------------------------------------
extern "C" void kernel_launch(void* const* d_in, const int* in_sizes, int n_in,
                              void* d_out, int out_size) {
    (void)in_sizes; (void)n_in; (void)out_size;
    const float* xdet = (const float*)d_in[0];
    const float* xcls = (const float*)d_in[1];
    const float* wrd  = (const float*)d_in[2];
    const float* wrc  = (const float*)d_in[3];
    const float* w1   = (const float*)d_in[4];
    const float* b1   = (const float*)d_in[5];
    const float* w2   = (const float*)d_in[6];
    const float* b2   = (const float*)d_in[7];
    float* out = (float*)d_out;

    cudaFuncSetAttribute(gemm1_tc, cudaFuncAttributeMaxDynamicSharedMemorySize, SMEM_DYN);
    cudaFuncSetAttribute(gemm2_tc, cudaFuncAttributeMaxDynamicSharedMemorySize, SMEM_DYN);

    prep_kernel<<<8192, 256>>>(out, wrd, wrc, w1, w2);
    router_kernel<<<NTOK / 8, 256>>>(xdet, xcls);
    positions_kernel<<<16, 256>>>();
    gather_kernel<<<MTOT, 192>>>(xdet, xcls);
    gemm1_tc<<<dim3(MLPD / 128, MTOT / 128), 256, SMEM_DYN>>>(b1);
    gemm2_tc<<<dim3(DM / 128, MTOT / 128), 256, SMEM_DYN>>>(b2, out);
}

// round 10
// speedup vs baseline: 1.1561x; 1.0320x over previous
#include <cuda_runtime.h>
#include <cuda_fp16.h>
#include <math.h>
#include <stdint.h>

// ---------------------------------------------------------------------------
// MoE block via mma.sync fp16 (fp32 accum), ldmatrix(.trans), 3-stage
// cp.async pipeline (race-free single-barrier mainloop), fused scatter
// epilogue. 6 launches. tcgen05 unavailable (toolchain targets sm_103).
// ---------------------------------------------------------------------------

#define NEXP 8
#define DM 768
#define MLPD 3072
#define CAP_DET 256
#define CAP_CLS 32
#define RPE 2304
#define MTOT (NEXP * RPE)
#define NTOK_DET 8192
#define NTOK_CLS 1024
#define NTOK (NTOK_DET + NTOK_CLS)

#define CHUNK 64
#define ASTR 72
#define BSTR 136
#define A_HALVES (128 * ASTR)
#define B_HALVES (CHUNK * BSTR)
#define STAGE_HALVES (A_HALVES + B_HALVES)
#define NBUF 3
#define SMEM_DYN (NBUF * STAGE_HALVES * 2)   // 107520 bytes

// --------------------------- scratch ---------------------------------------
__device__ __half g_xg[(size_t)MTOT * DM];
__device__ __half g_h [(size_t)MTOT * MLPD];
__device__ __half g_w1h[(size_t)NEXP * DM * MLPD];   // [E, K=768,  N=3072]
__device__ __half g_w2h[(size_t)NEXP * MLPD * DM];   // [E, K=3072, N=768]
__device__ float  g_wrt[2][NEXP * DM];
__device__ int    g_row_src[MTOT];
__device__ float  g_row_gate[MTOT];
__device__ signed char g_tok_e[NTOK][2];
__device__ float  g_tok_p[NTOK][2];

// --------------------------- helpers ---------------------------------------
__device__ __forceinline__ uint32_t smem_u32(const void* p) {
    uint32_t a;
    asm("{ .reg .u64 t; cvta.to.shared.u64 t, %1; cvt.u32.u64 %0, t; }"
        : "=r"(a) : "l"(p));
    return a;
}
__device__ __forceinline__ void cp_async16(uint32_t sdst, const void* gsrc) {
    asm volatile("cp.async.cg.shared.global [%0], [%1], 16;"
                 :: "r"(sdst), "l"(gsrc) : "memory");
}
__device__ __forceinline__ void cp_commit() {
    asm volatile("cp.async.commit_group;" ::: "memory");
}
template<int N>
__device__ __forceinline__ void cp_wait() {
    asm volatile("cp.async.wait_group %0;" :: "n"(N) : "memory");
}
__device__ __forceinline__ void ldsm_x4(uint32_t* r, uint32_t addr) {
    asm volatile("ldmatrix.sync.aligned.m8n8.x4.shared.b16 {%0,%1,%2,%3}, [%4];"
                 : "=r"(r[0]), "=r"(r[1]), "=r"(r[2]), "=r"(r[3]) : "r"(addr));
}
__device__ __forceinline__ void ldsm_x4_trans(uint32_t* r, uint32_t addr) {
    asm volatile("ldmatrix.sync.aligned.m8n8.x4.trans.shared.b16 {%0,%1,%2,%3}, [%4];"
                 : "=r"(r[0]), "=r"(r[1]), "=r"(r[2]), "=r"(r[3]) : "r"(addr));
}
__device__ __forceinline__ void mma_f16(float* d, const uint32_t* a,
                                        const uint32_t* b) {
    asm volatile(
        "mma.sync.aligned.m16n8k16.row.col.f32.f16.f16.f32 "
        "{%0,%1,%2,%3}, {%4,%5,%6,%7}, {%8,%9}, {%0,%1,%2,%3};"
        : "+f"(d[0]), "+f"(d[1]), "+f"(d[2]), "+f"(d[3])
        : "r"(a[0]), "r"(a[1]), "r"(a[2]), "r"(a[3]),
          "r"(b[0]), "r"(b[1]));
}
__device__ __forceinline__ float gelu_tanh(float x) {
    float x3 = x * x * x;
    return 0.5f * x * (1.0f + tanhf(0.7978845608028654f * (x + 0.044715f * x3)));
}

// ------------------- prep: zero out, init, transpose, convert ---------------
#define PREP_OUT4   (NTOK * DM / 4)
#define PREP_SRC    (MTOT)
#define PREP_WRT    (DM * NEXP)
#define PREP_W4     (NEXP * DM * MLPD / 4)
#define PREP_TOTAL  (PREP_OUT4 + PREP_SRC + PREP_WRT + 2 * PREP_W4)

__global__ void prep_kernel(float* __restrict__ out,
                            const float* __restrict__ wr0,
                            const float* __restrict__ wr1,
                            const float* __restrict__ w1,
                            const float* __restrict__ w2) {
    int stride = gridDim.x * blockDim.x;
    for (long long i = blockIdx.x * blockDim.x + threadIdx.x; i < PREP_TOTAL; i += stride) {
        if (i < PREP_OUT4) {
            ((float4*)out)[i] = make_float4(0.f, 0.f, 0.f, 0.f);
        } else if (i < PREP_OUT4 + PREP_SRC) {
            g_row_src[i - PREP_OUT4] = -1;
        } else if (i < PREP_OUT4 + PREP_SRC + PREP_WRT) {
            int j = (int)(i - PREP_OUT4 - PREP_SRC);
            int d = j / NEXP, e = j % NEXP;
            g_wrt[0][e * DM + d] = wr0[j];
            g_wrt[1][e * DM + d] = wr1[j];
        } else if (i < PREP_OUT4 + PREP_SRC + PREP_WRT + PREP_W4) {
            long long j = i - (PREP_OUT4 + PREP_SRC + PREP_WRT);
            float4 v = ((const float4*)w1)[j];
            __half2* d = (__half2*)g_w1h + j * 2;
            d[0] = __floats2half2_rn(v.x, v.y);
            d[1] = __floats2half2_rn(v.z, v.w);
        } else {
            long long j = i - (PREP_OUT4 + PREP_SRC + PREP_WRT + PREP_W4);
            float4 v = ((const float4*)w2)[j];
            __half2* d = (__half2*)g_w2h + j * 2;
            d[0] = __floats2half2_rn(v.x, v.y);
            d[1] = __floats2half2_rn(v.z, v.w);
        }
    }
}

// --------------------------- router (merged, smem weights) -------------------
__global__ __launch_bounds__(256)
void router_kernel(const float* __restrict__ xdet,
                   const float* __restrict__ xcls) {
    __shared__ float sw[NEXP * DM];
    int b = blockIdx.x;
    int tid = threadIdx.x;
    int which = (b < NTOK_DET / 8) ? 0 : 1;
    const float4* wsrc = (const float4*)g_wrt[which];
#pragma unroll
    for (int j = 0; j < 6; j++)
        ((float4*)sw)[j * 256 + tid] = wsrc[j * 256 + tid];
    __syncthreads();

    int wid = tid >> 5, lane = tid & 31;
    int t = b * 8 + wid;
    const float* xp = (t < NTOK_DET)
        ? (xdet + (size_t)t * DM)
        : (xcls + (size_t)(t - NTOK_DET) * DM);
    const float4* xr = (const float4*)xp;

    float acc[NEXP];
#pragma unroll
    for (int e = 0; e < NEXP; e++) acc[e] = 0.f;
#pragma unroll
    for (int it = 0; it < 6; it++) {
        int d4 = it * 32 + lane;
        float4 xv = xr[d4];
#pragma unroll
        for (int e = 0; e < NEXP; e++) {
            float4 wv = ((const float4*)(sw + e * DM))[d4];
            acc[e] += xv.x * wv.x + xv.y * wv.y + xv.z * wv.z + xv.w * wv.w;
        }
    }
#pragma unroll
    for (int e = 0; e < NEXP; e++) {
#pragma unroll
        for (int off = 16; off > 0; off >>= 1)
            acc[e] += __shfl_xor_sync(0xffffffffu, acc[e], off);
    }
    if (lane == 0) {
        float mx = acc[0];
#pragma unroll
        for (int e = 1; e < NEXP; e++) mx = fmaxf(mx, acc[e]);
        float p[NEXP]; float s = 0.f;
#pragma unroll
        for (int e = 0; e < NEXP; e++) { p[e] = expf(acc[e] - mx); s += p[e]; }
        float inv = 1.0f / s;
        int e0 = 0;
#pragma unroll
        for (int e = 1; e < NEXP; e++) if (p[e] > p[e0]) e0 = e;
        int e1 = (e0 == 0) ? 1 : 0;
#pragma unroll
        for (int e = 0; e < NEXP; e++) if (e != e0 && p[e] > p[e1]) e1 = e;
        g_tok_e[t][0] = (signed char)e0;
        g_tok_e[t][1] = (signed char)e1;
        g_tok_p[t][0] = p[e0] * inv;
        g_tok_p[t][1] = p[e1] * inv;
    }
}

// ------------------ positions (merged det+cls, grid 16) ----------------------
__global__ void positions_kernel() {
    __shared__ signed char se0[1024], se1[1024];
    __shared__ float sg0[1024], sg1[1024];
    int blk = blockIdx.x;
    int det = (blk < 8);
    int g = det ? blk : blk - 8;
    int S = det ? 1024 : 128;
    int C = det ? CAP_DET : CAP_CLS;
    int tok_base = det ? 0 : NTOK_DET;
    int row_off = det ? 0 : 2048;
    int tid = threadIdx.x;
    for (int t = tid; t < S; t += blockDim.x) {
        int gt = tok_base + g * S + t;
        se0[t] = g_tok_e[gt][0];
        se1[t] = g_tok_e[gt][1];
        sg0[t] = g_tok_p[gt][0];
        sg1[t] = g_tok_p[gt][1];
    }
    __syncthreads();
    int e = tid >> 5;
    int lane = tid & 31;
    int base = 0;
    int total = 2 * S;
    for (int j0 = 0; j0 < total; j0 += 32) {
        int j = j0 + lane;
        int exp_j = -1;
        if (j < total) exp_j = (j < S) ? (int)se0[j] : (int)se1[j - S];
        bool m = (exp_j == e);
        unsigned mask = __ballot_sync(0xffffffffu, m);
        if (m) {
            int pos = base + __popc(mask & ((1u << lane) - 1u));
            if (pos < C) {
                int t = (j < S) ? j : (j - S);
                int gt = tok_base + g * S + t;
                float gate = (j < S) ? sg0[t] : sg1[t];
                int row = e * RPE + row_off + g * C + pos;
                g_row_src[row] = gt;
                g_row_gate[row] = gate;
            }
        }
        base += __popc(mask);
    }
}

// --------------------------- gather (fp32 -> half) ---------------------------
__global__ void gather_kernel(const float* __restrict__ xdet,
                              const float* __restrict__ xcls) {
    int row = blockIdx.x;
    int i = threadIdx.x;
    int src = g_row_src[row];
    uint2 packed = make_uint2(0u, 0u);
    if (src >= 0) {
        const float* xp = (src < NTOK_DET)
            ? (xdet + (size_t)src * DM)
            : (xcls + (size_t)(src - NTOK_DET) * DM);
        float4 v = ((const float4*)xp)[i];
        __half2 h0 = __floats2half2_rn(v.x, v.y);
        __half2 h1 = __floats2half2_rn(v.z, v.w);
        packed.x = *(uint32_t*)&h0;
        packed.y = *(uint32_t*)&h1;
    }
    ((uint2*)(g_xg + (size_t)row * DM))[i] = packed;
}

// --------------------------- mma.sync fp16 GEMM ------------------------------
// FUSE=false: C[M,N] = gelu(A*W + b) stored half (GEMM1)
// FUSE=true : out[src(row)] += gate(row) * (A*W + b)   (GEMM2 + scatter)
// Race-free single-barrier multistage mainloop:
//   cp_wait -> __syncthreads -> issue(c+2) -> compute(c)
template<int K, int NTOT, bool FUSE>
__device__ __forceinline__ void tc_gemm(const __half* __restrict__ A,
                                        const __half* __restrict__ W,
                                        const float* __restrict__ bias,
                                        __half* __restrict__ C,
                                        float* __restrict__ out) {
    extern __shared__ __half smem[];
    int tid = threadIdx.x;
    int wid = tid >> 5, lane = tid & 31;
    int gid = lane >> 2, tig = lane & 3;
    int warp_m = wid & 1, warp_n = wid >> 1;
    int m_base = warp_m * 64, n_base = warp_n * 32;
    int bx = blockIdx.x, by = blockIdx.y;
    int e = (by * 128) / RPE;
    const __half* Ab = A + (size_t)by * 128 * K;
    const __half* Wb = W + (size_t)e * K * NTOT + (size_t)bx * 128;

    uint32_t a_off = (uint32_t)((m_base + (lane & 15)) * ASTR + ((lane >> 4) << 3));
    uint32_t b_off = (uint32_t)((((lane >> 3) & 1) * 8 + (lane & 7)) * BSTR
                                + n_base + ((lane >> 4) << 3));

    float acc[4][4][4];
#pragma unroll
    for (int mi = 0; mi < 4; mi++)
#pragma unroll
        for (int ni = 0; ni < 4; ni++)
#pragma unroll
            for (int q = 0; q < 4; q++) acc[mi][ni][q] = 0.f;

    const int NC = K / CHUNK;
    uint32_t sbase = smem_u32(smem);

    auto issue_stage = [&](int c) {
        int buf = c % NBUF;
        uint32_t as = sbase + (uint32_t)(buf * STAGE_HALVES) * 2u;
        uint32_t bs = as + (uint32_t)A_HALVES * 2u;
        int kc = c * CHUNK;
#pragma unroll
        for (int j = 0; j < 4; j++) {
            int idx = j * 256 + tid;
            int row = idx >> 3, seg = idx & 7;
            cp_async16(as + (uint32_t)(row * ASTR + seg * 8) * 2u,
                       Ab + (size_t)row * K + kc + seg * 8);
        }
#pragma unroll
        for (int j = 0; j < 4; j++) {
            int idx = j * 256 + tid;
            int row = idx >> 4, seg = idx & 15;
            cp_async16(bs + (uint32_t)(row * BSTR + seg * 8) * 2u,
                       Wb + (size_t)(kc + row) * NTOT + seg * 8);
        }
        cp_commit();
    };

    issue_stage(0);
    if (NC > 1) issue_stage(1);
    for (int c = 0; c < NC; c++) {
        if (c + 1 < NC) cp_wait<1>(); else cp_wait<0>();
        __syncthreads();                       // publishes chunk c; fences c-1 reads
        if (c + 2 < NC) issue_stage(c + 2);    // safe: all warps done with this buf

        uint32_t as = sbase + (uint32_t)((c % NBUF) * STAGE_HALVES) * 2u;
        uint32_t bs = as + (uint32_t)A_HALVES * 2u;
        uint32_t a_base = as + a_off * 2u;
        uint32_t b_base = bs + b_off * 2u;
#pragma unroll
        for (int kk = 0; kk < CHUNK; kk += 16) {
            uint32_t afr[4][4];
#pragma unroll
            for (int mi = 0; mi < 4; mi++)
                ldsm_x4(afr[mi], a_base + (uint32_t)(mi * 16 * ASTR + kk) * 2u);
            uint32_t bfr[2][4];
#pragma unroll
            for (int p = 0; p < 2; p++)
                ldsm_x4_trans(bfr[p], b_base + (uint32_t)(kk * BSTR + p * 16) * 2u);
#pragma unroll
            for (int mi = 0; mi < 4; mi++)
#pragma unroll
                for (int ni = 0; ni < 4; ni++)
                    mma_f16(acc[mi][ni], afr[mi], &bfr[ni >> 1][(ni & 1) * 2]);
        }
    }

    if (!FUSE) {
#pragma unroll
        for (int ni = 0; ni < 4; ni++) {
            int cb = bx * 128 + n_base + ni * 8 + 2 * tig;
            float b0 = bias[e * NTOT + cb];
            float b1 = bias[e * NTOT + cb + 1];
#pragma unroll
            for (int mi = 0; mi < 4; mi++) {
                int r0 = by * 128 + m_base + mi * 16 + gid;
                float v0 = gelu_tanh(acc[mi][ni][0] + b0);
                float v1 = gelu_tanh(acc[mi][ni][1] + b1);
                float v2 = gelu_tanh(acc[mi][ni][2] + b0);
                float v3 = gelu_tanh(acc[mi][ni][3] + b1);
                *(__half2*)(C + (size_t)r0 * NTOT + cb)       = __floats2half2_rn(v0, v1);
                *(__half2*)(C + (size_t)(r0 + 8) * NTOT + cb) = __floats2half2_rn(v2, v3);
            }
        }
    } else {
        int rsrc[8]; float rg[8];
#pragma unroll
        for (int mi = 0; mi < 4; mi++) {
            int r0 = by * 128 + m_base + mi * 16 + gid;
            rsrc[mi * 2]     = __ldg(&g_row_src[r0]);
            rsrc[mi * 2 + 1] = __ldg(&g_row_src[r0 + 8]);
            rg[mi * 2]     = rsrc[mi * 2]     >= 0 ? __ldg(&g_row_gate[r0])     : 0.f;
            rg[mi * 2 + 1] = rsrc[mi * 2 + 1] >= 0 ? __ldg(&g_row_gate[r0 + 8]) : 0.f;
        }
#pragma unroll
        for (int ni = 0; ni < 4; ni++) {
            int cb = bx * 128 + n_base + ni * 8 + 2 * tig;
            float b0 = bias[e * NTOT + cb];
            float b1 = bias[e * NTOT + cb + 1];
#pragma unroll
            for (int mi = 0; mi < 4; mi++) {
                int src0 = rsrc[mi * 2], src1 = rsrc[mi * 2 + 1];
                if (src0 >= 0) {
                    float g0 = rg[mi * 2];
                    atomicAdd(out + (size_t)src0 * DM + cb,     g0 * (acc[mi][ni][0] + b0));
                    atomicAdd(out + (size_t)src0 * DM + cb + 1, g0 * (acc[mi][ni][1] + b1));
                }
                if (src1 >= 0) {
                    float g1 = rg[mi * 2 + 1];
                    atomicAdd(out + (size_t)src1 * DM + cb,     g1 * (acc[mi][ni][2] + b0));
                    atomicAdd(out + (size_t)src1 * DM + cb + 1, g1 * (acc[mi][ni][3] + b1));
                }
            }
        }
    }
}

__global__ __launch_bounds__(256, 2)
void gemm1_tc(const float* __restrict__ b1) {
    tc_gemm<DM, MLPD, false>(g_xg, g_w1h, b1, g_h, nullptr);
}
__global__ __launch_bounds__(256, 2)
void gemm2_tc(const float* __restrict__ b2, float* __restrict__ out) {
    tc_gemm<MLPD, DM, true>(g_h, g_w2h, b2, nullptr, out);
}

// --------------------------- launch -----------------------------------------
extern "C" void kernel_launch(void* const* d_in, const int* in_sizes, int n_in,
                              void* d_out, int out_size) {
    (void)in_sizes; (void)n_in; (void)out_size;
    const float* xdet = (const float*)d_in[0];
    const float* xcls = (const float*)d_in[1];
    const float* wrd  = (const float*)d_in[2];
    const float* wrc  = (const float*)d_in[3];
    const float* w1   = (const float*)d_in[4];
    const float* b1   = (const float*)d_in[5];
    const float* w2   = (const float*)d_in[6];
    const float* b2   = (const float*)d_in[7];
    float* out = (float*)d_out;

    cudaFuncSetAttribute(gemm1_tc, cudaFuncAttributeMaxDynamicSharedMemorySize, SMEM_DYN);
    cudaFuncSetAttribute(gemm2_tc, cudaFuncAttributeMaxDynamicSharedMemorySize, SMEM_DYN);

    prep_kernel<<<8192, 256>>>(out, wrd, wrc, w1, w2);
    router_kernel<<<NTOK / 8, 256>>>(xdet, xcls);
    positions_kernel<<<16, 256>>>();
    gather_kernel<<<MTOT, 192>>>(xdet, xcls);
    gemm1_tc<<<dim3(MLPD / 128, MTOT / 128), 256, SMEM_DYN>>>(b1);
    gemm2_tc<<<dim3(DM / 128, MTOT / 128), 256, SMEM_DYN>>>(b2, out);
}

// round 11
// speedup vs baseline: 1.1681x; 1.0104x over previous
#include <cuda_runtime.h>
#include <cuda_fp16.h>
#include <math.h>
#include <stdint.h>

// ---------------------------------------------------------------------------
// MoE block via mma.sync fp16 (fp32 accum), ldmatrix(.trans), 3-stage
// cp.async pipeline (single-barrier mainloop), fused scatter epilogue,
// forked-stream prep overlap. tcgen05 unavailable (toolchain targets sm_103).
// ---------------------------------------------------------------------------

#define NEXP 8
#define DM 768
#define MLPD 3072
#define CAP_DET 256
#define CAP_CLS 32
#define RPE 2304
#define MTOT (NEXP * RPE)
#define NTOK_DET 8192
#define NTOK_CLS 1024
#define NTOK (NTOK_DET + NTOK_CLS)

#define CHUNK 64
#define ASTR 72
#define BSTR 136
#define A_HALVES (128 * ASTR)
#define B_HALVES (CHUNK * BSTR)
#define STAGE_HALVES (A_HALVES + B_HALVES)
#define NBUF 3
#define SMEM_DYN (NBUF * STAGE_HALVES * 2)   // 107520 bytes

// --------------------------- scratch ---------------------------------------
__device__ __half g_xg[(size_t)MTOT * DM];
__device__ __half g_h [(size_t)MTOT * MLPD];
__device__ __half g_w1h[(size_t)NEXP * DM * MLPD];   // [E, K=768,  N=3072]
__device__ __half g_w2h[(size_t)NEXP * MLPD * DM];   // [E, K=3072, N=768]
__device__ float  g_wrt[2][NEXP * DM];
__device__ int    g_row_src[MTOT];
__device__ float  g_row_gate[MTOT];
__device__ signed char g_tok_e[NTOK][2];
__device__ float  g_tok_p[NTOK][2];

// --------------------------- helpers ---------------------------------------
__device__ __forceinline__ uint32_t smem_u32(const void* p) {
    uint32_t a;
    asm("{ .reg .u64 t; cvta.to.shared.u64 t, %1; cvt.u32.u64 %0, t; }"
        : "=r"(a) : "l"(p));
    return a;
}
__device__ __forceinline__ void cp_async16(uint32_t sdst, const void* gsrc) {
    asm volatile("cp.async.cg.shared.global [%0], [%1], 16;"
                 :: "r"(sdst), "l"(gsrc) : "memory");
}
__device__ __forceinline__ void cp_commit() {
    asm volatile("cp.async.commit_group;" ::: "memory");
}
template<int N>
__device__ __forceinline__ void cp_wait() {
    asm volatile("cp.async.wait_group %0;" :: "n"(N) : "memory");
}
__device__ __forceinline__ void ldsm_x4(uint32_t* r, uint32_t addr) {
    asm volatile("ldmatrix.sync.aligned.m8n8.x4.shared.b16 {%0,%1,%2,%3}, [%4];"
                 : "=r"(r[0]), "=r"(r[1]), "=r"(r[2]), "=r"(r[3]) : "r"(addr));
}
__device__ __forceinline__ void ldsm_x4_trans(uint32_t* r, uint32_t addr) {
    asm volatile("ldmatrix.sync.aligned.m8n8.x4.trans.shared.b16 {%0,%1,%2,%3}, [%4];"
                 : "=r"(r[0]), "=r"(r[1]), "=r"(r[2]), "=r"(r[3]) : "r"(addr));
}
__device__ __forceinline__ void mma_f16(float* d, const uint32_t* a,
                                        const uint32_t* b) {
    asm volatile(
        "mma.sync.aligned.m16n8k16.row.col.f32.f16.f16.f32 "
        "{%0,%1,%2,%3}, {%4,%5,%6,%7}, {%8,%9}, {%0,%1,%2,%3};"
        : "+f"(d[0]), "+f"(d[1]), "+f"(d[2]), "+f"(d[3])
        : "r"(a[0]), "r"(a[1]), "r"(a[2]), "r"(a[3]),
          "r"(b[0]), "r"(b[1]));
}
__device__ __forceinline__ float gelu_tanh(float x) {
    float x3 = x * x * x;
    return 0.5f * x * (1.0f + tanhf(0.7978845608028654f * (x + 0.044715f * x3)));
}

// --------------------- branch s2: weight converts + zero --------------------
#define W4_COUNT   (NEXP * DM * MLPD / 4)        // 4718592 float4 per tensor
#define OUT4_COUNT (NTOK * DM / 4)               // 1769472 float4

__global__ void convw1_kernel(const float* __restrict__ w1) {
    long long stride = (long long)gridDim.x * blockDim.x;
    for (long long j = blockIdx.x * (long long)blockDim.x + threadIdx.x;
         j < W4_COUNT; j += stride) {
        float4 v = ((const float4*)w1)[j];
        __half2* d = (__half2*)g_w1h + j * 2;
        d[0] = __floats2half2_rn(v.x, v.y);
        d[1] = __floats2half2_rn(v.z, v.w);
    }
}

__global__ void convw2z_kernel(const float* __restrict__ w2,
                               float* __restrict__ out) {
    long long stride = (long long)gridDim.x * blockDim.x;
    const long long total = W4_COUNT + OUT4_COUNT;
    for (long long i = blockIdx.x * (long long)blockDim.x + threadIdx.x;
         i < total; i += stride) {
        if (i < W4_COUNT) {
            float4 v = ((const float4*)w2)[i];
            __half2* d = (__half2*)g_w2h + i * 2;
            d[0] = __floats2half2_rn(v.x, v.y);
            d[1] = __floats2half2_rn(v.z, v.w);
        } else {
            ((float4*)out)[i - W4_COUNT] = make_float4(0.f, 0.f, 0.f, 0.f);
        }
    }
}

// -------------------- router weight transpose [D,E] -> [E,D] -----------------
__global__ void wrt_kernel(const float* __restrict__ wr0,
                           const float* __restrict__ wr1) {
    int i = blockIdx.x * blockDim.x + threadIdx.x;
    if (i >= DM * NEXP) return;
    int d = i / NEXP, e = i % NEXP;
    g_wrt[0][e * DM + d] = wr0[i];
    g_wrt[1][e * DM + d] = wr1[i];
}

// --------------------------- router (merged, smem weights) -------------------
// Also initializes g_row_src (16 ints per block; 1152 blocks * 16 = MTOT).
__global__ __launch_bounds__(256)
void router_kernel(const float* __restrict__ xdet,
                   const float* __restrict__ xcls) {
    __shared__ float sw[NEXP * DM];
    int b = blockIdx.x;
    int tid = threadIdx.x;
    if (tid < 16) g_row_src[b * 16 + tid] = -1;
    int which = (b < NTOK_DET / 8) ? 0 : 1;
    const float4* wsrc = (const float4*)g_wrt[which];
#pragma unroll
    for (int j = 0; j < 6; j++)
        ((float4*)sw)[j * 256 + tid] = wsrc[j * 256 + tid];
    __syncthreads();

    int wid = tid >> 5, lane = tid & 31;
    int t = b * 8 + wid;
    const float* xp = (t < NTOK_DET)
        ? (xdet + (size_t)t * DM)
        : (xcls + (size_t)(t - NTOK_DET) * DM);
    const float4* xr = (const float4*)xp;

    float acc[NEXP];
#pragma unroll
    for (int e = 0; e < NEXP; e++) acc[e] = 0.f;
#pragma unroll
    for (int it = 0; it < 6; it++) {
        int d4 = it * 32 + lane;
        float4 xv = xr[d4];
#pragma unroll
        for (int e = 0; e < NEXP; e++) {
            float4 wv = ((const float4*)(sw + e * DM))[d4];
            acc[e] += xv.x * wv.x + xv.y * wv.y + xv.z * wv.z + xv.w * wv.w;
        }
    }
#pragma unroll
    for (int e = 0; e < NEXP; e++) {
#pragma unroll
        for (int off = 16; off > 0; off >>= 1)
            acc[e] += __shfl_xor_sync(0xffffffffu, acc[e], off);
    }
    if (lane == 0) {
        float mx = acc[0];
#pragma unroll
        for (int e = 1; e < NEXP; e++) mx = fmaxf(mx, acc[e]);
        float p[NEXP]; float s = 0.f;
#pragma unroll
        for (int e = 0; e < NEXP; e++) { p[e] = expf(acc[e] - mx); s += p[e]; }
        float inv = 1.0f / s;
        int e0 = 0;
#pragma unroll
        for (int e = 1; e < NEXP; e++) if (p[e] > p[e0]) e0 = e;
        int e1 = (e0 == 0) ? 1 : 0;
#pragma unroll
        for (int e = 0; e < NEXP; e++) if (e != e0 && p[e] > p[e1]) e1 = e;
        g_tok_e[t][0] = (signed char)e0;
        g_tok_e[t][1] = (signed char)e1;
        g_tok_p[t][0] = p[e0] * inv;
        g_tok_p[t][1] = p[e1] * inv;
    }
}

// ------------------ positions (merged det+cls, grid 16) ----------------------
__global__ void positions_kernel() {
    __shared__ signed char se0[1024], se1[1024];
    __shared__ float sg0[1024], sg1[1024];
    int blk = blockIdx.x;
    int det = (blk < 8);
    int g = det ? blk : blk - 8;
    int S = det ? 1024 : 128;
    int C = det ? CAP_DET : CAP_CLS;
    int tok_base = det ? 0 : NTOK_DET;
    int row_off = det ? 0 : 2048;
    int tid = threadIdx.x;
    for (int t = tid; t < S; t += blockDim.x) {
        int gt = tok_base + g * S + t;
        se0[t] = g_tok_e[gt][0];
        se1[t] = g_tok_e[gt][1];
        sg0[t] = g_tok_p[gt][0];
        sg1[t] = g_tok_p[gt][1];
    }
    __syncthreads();
    int e = tid >> 5;
    int lane = tid & 31;
    int base = 0;
    int total = 2 * S;
    for (int j0 = 0; j0 < total; j0 += 32) {
        int j = j0 + lane;
        int exp_j = -1;
        if (j < total) exp_j = (j < S) ? (int)se0[j] : (int)se1[j - S];
        bool m = (exp_j == e);
        unsigned mask = __ballot_sync(0xffffffffu, m);
        if (m) {
            int pos = base + __popc(mask & ((1u << lane) - 1u));
            if (pos < C) {
                int t = (j < S) ? j : (j - S);
                int gt = tok_base + g * S + t;
                float gate = (j < S) ? sg0[t] : sg1[t];
                int row = e * RPE + row_off + g * C + pos;
                g_row_src[row] = gt;
                g_row_gate[row] = gate;
            }
        }
        base += __popc(mask);
    }
}

// --------------------------- gather (fp32 -> half) ---------------------------
__global__ void gather_kernel(const float* __restrict__ xdet,
                              const float* __restrict__ xcls) {
    int row = blockIdx.x;
    int i = threadIdx.x;
    int src = g_row_src[row];
    uint2 packed = make_uint2(0u, 0u);
    if (src >= 0) {
        const float* xp = (src < NTOK_DET)
            ? (xdet + (size_t)src * DM)
            : (xcls + (size_t)(src - NTOK_DET) * DM);
        float4 v = ((const float4*)xp)[i];
        __half2 h0 = __floats2half2_rn(v.x, v.y);
        __half2 h1 = __floats2half2_rn(v.z, v.w);
        packed.x = *(uint32_t*)&h0;
        packed.y = *(uint32_t*)&h1;
    }
    ((uint2*)(g_xg + (size_t)row * DM))[i] = packed;
}

// --------------------------- mma.sync fp16 GEMM ------------------------------
// FUSE=false: C[M,N] = gelu(A*W + b) stored half (GEMM1)
// FUSE=true : out[src(row)] += gate(row) * (A*W + b)   (GEMM2 + scatter)
template<int K, int NTOT, bool FUSE>
__device__ __forceinline__ void tc_gemm(const __half* __restrict__ A,
                                        const __half* __restrict__ W,
                                        const float* __restrict__ bias,
                                        __half* __restrict__ C,
                                        float* __restrict__ out) {
    extern __shared__ __half smem[];
    int tid = threadIdx.x;
    int wid = tid >> 5, lane = tid & 31;
    int gid = lane >> 2, tig = lane & 3;
    int warp_m = wid & 1, warp_n = wid >> 1;
    int m_base = warp_m * 64, n_base = warp_n * 32;
    int bx = blockIdx.x, by = blockIdx.y;
    int e = (by * 128) / RPE;
    const __half* Ab = A + (size_t)by * 128 * K;
    const __half* Wb = W + (size_t)e * K * NTOT + (size_t)bx * 128;

    uint32_t a_off = (uint32_t)((m_base + (lane & 15)) * ASTR + ((lane >> 4) << 3));
    uint32_t b_off = (uint32_t)((((lane >> 3) & 1) * 8 + (lane & 7)) * BSTR
                                + n_base + ((lane >> 4) << 3));

    float acc[4][4][4];
#pragma unroll
    for (int mi = 0; mi < 4; mi++)
#pragma unroll
        for (int ni = 0; ni < 4; ni++)
#pragma unroll
            for (int q = 0; q < 4; q++) acc[mi][ni][q] = 0.f;

    const int NC = K / CHUNK;
    uint32_t sbase = smem_u32(smem);

    auto issue_stage = [&](int c) {
        int buf = c % NBUF;
        uint32_t as = sbase + (uint32_t)(buf * STAGE_HALVES) * 2u;
        uint32_t bs = as + (uint32_t)A_HALVES * 2u;
        int kc = c * CHUNK;
#pragma unroll
        for (int j = 0; j < 4; j++) {
            int idx = j * 256 + tid;
            int row = idx >> 3, seg = idx & 7;
            cp_async16(as + (uint32_t)(row * ASTR + seg * 8) * 2u,
                       Ab + (size_t)row * K + kc + seg * 8);
        }
#pragma unroll
        for (int j = 0; j < 4; j++) {
            int idx = j * 256 + tid;
            int row = idx >> 4, seg = idx & 15;
            cp_async16(bs + (uint32_t)(row * BSTR + seg * 8) * 2u,
                       Wb + (size_t)(kc + row) * NTOT + seg * 8);
        }
        cp_commit();
    };

    issue_stage(0);
    if (NC > 1) issue_stage(1);
    for (int c = 0; c < NC; c++) {
        if (c + 1 < NC) cp_wait<1>(); else cp_wait<0>();
        __syncthreads();                       // publishes chunk c; fences c-1 reads
        if (c + 2 < NC) issue_stage(c + 2);    // safe: all warps done with this buf

        uint32_t as = sbase + (uint32_t)((c % NBUF) * STAGE_HALVES) * 2u;
        uint32_t bs = as + (uint32_t)A_HALVES * 2u;
        uint32_t a_base = as + a_off * 2u;
        uint32_t b_base = bs + b_off * 2u;
#pragma unroll
        for (int kk = 0; kk < CHUNK; kk += 16) {
            uint32_t afr[4][4];
#pragma unroll
            for (int mi = 0; mi < 4; mi++)
                ldsm_x4(afr[mi], a_base + (uint32_t)(mi * 16 * ASTR + kk) * 2u);
            uint32_t bfr[2][4];
#pragma unroll
            for (int p = 0; p < 2; p++)
                ldsm_x4_trans(bfr[p], b_base + (uint32_t)(kk * BSTR + p * 16) * 2u);
#pragma unroll
            for (int mi = 0; mi < 4; mi++)
#pragma unroll
                for (int ni = 0; ni < 4; ni++)
                    mma_f16(acc[mi][ni], afr[mi], &bfr[ni >> 1][(ni & 1) * 2]);
        }
    }

    if (!FUSE) {
#pragma unroll
        for (int ni = 0; ni < 4; ni++) {
            int cb = bx * 128 + n_base + ni * 8 + 2 * tig;
            float b0 = bias[e * NTOT + cb];
            float b1 = bias[e * NTOT + cb + 1];
#pragma unroll
            for (int mi = 0; mi < 4; mi++) {
                int r0 = by * 128 + m_base + mi * 16 + gid;
                float v0 = gelu_tanh(acc[mi][ni][0] + b0);
                float v1 = gelu_tanh(acc[mi][ni][1] + b1);
                float v2 = gelu_tanh(acc[mi][ni][2] + b0);
                float v3 = gelu_tanh(acc[mi][ni][3] + b1);
                *(__half2*)(C + (size_t)r0 * NTOT + cb)       = __floats2half2_rn(v0, v1);
                *(__half2*)(C + (size_t)(r0 + 8) * NTOT + cb) = __floats2half2_rn(v2, v3);
            }
        }
    } else {
        int rsrc[8]; float rg[8];
#pragma unroll
        for (int mi = 0; mi < 4; mi++) {
            int r0 = by * 128 + m_base + mi * 16 + gid;
            rsrc[mi * 2]     = __ldg(&g_row_src[r0]);
            rsrc[mi * 2 + 1] = __ldg(&g_row_src[r0 + 8]);
            rg[mi * 2]     = rsrc[mi * 2]     >= 0 ? __ldg(&g_row_gate[r0])     : 0.f;
            rg[mi * 2 + 1] = rsrc[mi * 2 + 1] >= 0 ? __ldg(&g_row_gate[r0 + 8]) : 0.f;
        }
#pragma unroll
        for (int ni = 0; ni < 4; ni++) {
            int cb = bx * 128 + n_base + ni * 8 + 2 * tig;
            float b0 = bias[e * NTOT + cb];
            float b1 = bias[e * NTOT + cb + 1];
#pragma unroll
            for (int mi = 0; mi < 4; mi++) {
                int src0 = rsrc[mi * 2], src1 = rsrc[mi * 2 + 1];
                if (src0 >= 0) {
                    float g0 = rg[mi * 2];
                    atomicAdd(out + (size_t)src0 * DM + cb,     g0 * (acc[mi][ni][0] + b0));
                    atomicAdd(out + (size_t)src0 * DM + cb + 1, g0 * (acc[mi][ni][1] + b1));
                }
                if (src1 >= 0) {
                    float g1 = rg[mi * 2 + 1];
                    atomicAdd(out + (size_t)src1 * DM + cb,     g1 * (acc[mi][ni][2] + b0));
                    atomicAdd(out + (size_t)src1 * DM + cb + 1, g1 * (acc[mi][ni][3] + b1));
                }
            }
        }
    }
}

__global__ __launch_bounds__(256, 2)
void gemm1_tc(const float* __restrict__ b1) {
    tc_gemm<DM, MLPD, false>(g_xg, g_w1h, b1, g_h, nullptr);
}
__global__ __launch_bounds__(256, 2)
void gemm2_tc(const float* __restrict__ b2, float* __restrict__ out) {
    tc_gemm<MLPD, DM, true>(g_h, g_w2h, b2, nullptr, out);
}

// --------------------------- launch -----------------------------------------
extern "C" void kernel_launch(void* const* d_in, const int* in_sizes, int n_in,
                              void* d_out, int out_size) {
    (void)in_sizes; (void)n_in; (void)out_size;
    const float* xdet = (const float*)d_in[0];
    const float* xcls = (const float*)d_in[1];
    const float* wrd  = (const float*)d_in[2];
    const float* wrc  = (const float*)d_in[3];
    const float* w1   = (const float*)d_in[4];
    const float* b1   = (const float*)d_in[5];
    const float* w2   = (const float*)d_in[6];
    const float* b2   = (const float*)d_in[7];
    float* out = (float*)d_out;

    static cudaStream_t s2 = nullptr;
    static cudaEvent_t ev0 = nullptr, ev1 = nullptr, ev2 = nullptr;
    if (!s2) {
        cudaStreamCreateWithFlags(&s2, cudaStreamNonBlocking);
        cudaEventCreateWithFlags(&ev0, cudaEventDisableTiming);
        cudaEventCreateWithFlags(&ev1, cudaEventDisableTiming);
        cudaEventCreateWithFlags(&ev2, cudaEventDisableTiming);
        cudaFuncSetAttribute(gemm1_tc, cudaFuncAttributeMaxDynamicSharedMemorySize, SMEM_DYN);
        cudaFuncSetAttribute(gemm2_tc, cudaFuncAttributeMaxDynamicSharedMemorySize, SMEM_DYN);
    }

    // fork: weight conversion branch on s2
    cudaEventRecord(ev0, 0);
    cudaStreamWaitEvent(s2, ev0, 0);
    convw1_kernel<<<2048, 256, 0, s2>>>(w1);
    cudaEventRecord(ev1, s2);
    convw2z_kernel<<<2048, 256, 0, s2>>>(w2, out);
    cudaEventRecord(ev2, s2);

    // main branch: routing pipeline
    wrt_kernel<<<(DM * NEXP + 255) / 256, 256>>>(wrd, wrc);
    router_kernel<<<NTOK / 8, 256>>>(xdet, xcls);
    positions_kernel<<<16, 256>>>();
    gather_kernel<<<MTOT, 192>>>(xdet, xcls);

    // join and run GEMMs
    cudaStreamWaitEvent(0, ev1, 0);
    gemm1_tc<<<dim3(MLPD / 128, MTOT / 128), 256, SMEM_DYN>>>(b1);
    cudaStreamWaitEvent(0, ev2, 0);
    gemm2_tc<<<dim3(DM / 128, MTOT / 128), 256, SMEM_DYN>>>(b2, out);
}